// round 12
// baseline (speedup 1.0000x reference)
#include <cuda_runtime.h>
#include <cuda_fp16.h>
#include <cstdint>

// ---------------------------------------------------------------------------
// PopulationGNN: 4-layer GCN, N=50000, IN_DIM=2000, HID=64, E=1.6M
// CSR build once (packed src+weight), then per layer:
// TF32 mma GEMM (cp.async.cg 3-stage, fp16 out) -> warp-per-node gather
// (packed int4 edge loads) -> fused BN stats+finalize+norm (256-block ticket
// + epoch spin barrier, single AGG read) -> emb accumulate.
// ---------------------------------------------------------------------------

#define HID 64
#define MAXN 50048
#define MAXE 1600256
#define STATS_BLOCKS 256
#define SBS 256
#define MAXSB 256

__device__ __align__(16) __half g_XWH[MAXN * HID];   // fp16 XW (gather input)
__device__ __align__(16) float g_AGG[MAXN * HID];
__device__ __align__(16) float g_OUT0[MAXN * HID];
__device__ __align__(16) float g_OUT1[MAXN * HID];
__device__ int   g_DEGI[MAXN];
__device__ float g_DINV[MAXN];
__device__ __align__(16) int2 g_EPK[MAXE];           // packed {src, weight-bits}
__device__ int   g_ROWPTR[MAXN + 1];
__device__ int   g_CUR[MAXN];
__device__ int   g_ROWEXC[MAXN];
__device__ int   g_BTOT[MAXSB];
__device__ int   g_BOFF[MAXSB];
__device__ int   g_IS32;
__device__ unsigned int g_TICKET;
__device__ int   g_EPOCH;                            // layer completion epoch
__device__ __align__(16) float g_PART[STATS_BLOCKS * 128];
__device__ __align__(16) float g_SS[132];

// ---------------------------------------------------------------------------
// Setup: fused init+detect, then CSR build
// ---------------------------------------------------------------------------

__global__ void init_detect_kernel(const int* __restrict__ words, int n, int E) {
    int i = blockIdx.x * blockDim.x + threadIdx.x;
    if (i < n) g_DEGI[i] = 0;
    if (i == 0) { g_IS32 = 0; g_EPOCH = 0; g_TICKET = 0; }
    int idx = 2 * i + 1;
    if (idx < E && words[idx] != 0)
        atomicOr(&g_IS32, 1);
}

__device__ __forceinline__ void decode_edge(const int* __restrict__ words, int E, int e,
                                            int& s, int& d) {
    if (g_IS32) {
        s = words[e];
        d = words[E + e];
    } else {
        s = words[2 * e];
        d = words[2 * E + 2 * e];
    }
}

__global__ void count_kernel(const int* __restrict__ words, int E) {
    int e = blockIdx.x * blockDim.x + threadIdx.x;
    if (e < E) {
        int s, d;
        decode_edge(words, E, e, s, d);
        atomicAdd(&g_DEGI[d], 1);
    }
}

__global__ void dinv_kernel(int n) {
    int i = blockIdx.x * blockDim.x + threadIdx.x;
    if (i < n) g_DINV[i] = rsqrtf((float)g_DEGI[i] + 1.0f);
}

__global__ void scan1_kernel(int n) {
    __shared__ int sm[SBS];
    int t = threadIdx.x;
    int i = blockIdx.x * SBS + t;
    int v = (i < n) ? g_DEGI[i] : 0;
    sm[t] = v;
    __syncthreads();
#pragma unroll
    for (int off = 1; off < SBS; off <<= 1) {
        int y = (t >= off) ? sm[t - off] : 0;
        __syncthreads();
        sm[t] += y;
        __syncthreads();
    }
    if (i < n) g_ROWEXC[i] = sm[t] - v;
    if (t == SBS - 1) g_BTOT[blockIdx.x] = sm[t];
}

__global__ void scan2_kernel(int nb) {
    __shared__ int sm[SBS];
    int t = threadIdx.x;
    int v = (t < nb) ? g_BTOT[t] : 0;
    sm[t] = v;
    __syncthreads();
#pragma unroll
    for (int off = 1; off < SBS; off <<= 1) {
        int y = (t >= off) ? sm[t - off] : 0;
        __syncthreads();
        sm[t] += y;
        __syncthreads();
    }
    if (t < nb) g_BOFF[t] = sm[t] - v;
}

__global__ void scan3_kernel(int n, int E) {
    int i = blockIdx.x * blockDim.x + threadIdx.x;
    if (i < n) {
        int r = g_ROWEXC[i] + g_BOFF[i / SBS];
        g_ROWPTR[i] = r;
        g_CUR[i] = r;
    }
    if (i == 0) g_ROWPTR[n] = E;
}

__global__ void fill_kernel(const int* __restrict__ words, int E) {
    int e = blockIdx.x * blockDim.x + threadIdx.x;
    if (e < E) {
        int s, d;
        decode_edge(words, E, e, s, d);
        int pos = atomicAdd(&g_CUR[d], 1);
        float w = g_DINV[s] * g_DINV[d];
        g_EPK[pos] = make_int2(s, __float_as_int(w));
    }
}

// ---------------------------------------------------------------------------
// TF32 GEMM, cp.async.cg 3-stage pipeline. A[M,K] @ W[K,64] -> g_XWH (fp16).
// BM=128, BN=64, BK=16, 256 thr, 8 warps, warp tile 32x32 via m16n8k8.
// ---------------------------------------------------------------------------

#define NSTAGE 3

__device__ __forceinline__ uint32_t f2tf32(float x) {
    uint32_t out;
    asm("cvt.rna.tf32.f32 %0, %1;" : "=r"(out) : "f"(x));
    return out;
}

__device__ __forceinline__ void mma_tf32(float& c0, float& c1, float& c2, float& c3,
                                         uint32_t a0, uint32_t a1, uint32_t a2, uint32_t a3,
                                         uint32_t b0, uint32_t b1) {
    asm volatile(
        "mma.sync.aligned.m16n8k8.row.col.f32.tf32.tf32.f32 "
        "{%0,%1,%2,%3}, {%4,%5,%6,%7}, {%8,%9}, {%0,%1,%2,%3};"
        : "+f"(c0), "+f"(c1), "+f"(c2), "+f"(c3)
        : "r"(a0), "r"(a1), "r"(a2), "r"(a3), "r"(b0), "r"(b1));
}

__device__ __forceinline__ void cp16(uint32_t smem_addr, const float* gptr) {
    asm volatile("cp.async.cg.shared.global [%0], [%1], 16;"
                 :: "r"(smem_addr), "l"(gptr));
}

__global__ void __launch_bounds__(256, 3)
gemm_tf32_kernel(const float* __restrict__ feat, int src_sel,
                 const float* __restrict__ W, int M, int K) {
    __shared__ float As[NSTAGE][128][20];   // banks (20m+k)%32 conflict-free
    __shared__ float Bs[NSTAGE][16][72];    // banks (8k+n)%32  conflict-free

    const float* A = (src_sel == 0) ? feat : (src_sel == 1 ? g_OUT0 : g_OUT1);

    int t = threadIdx.x;
    int m0 = blockIdx.x * 128;
    int warp = t >> 5;
    int lane = t & 31;
    int wm = (warp >> 1) * 32;
    int wn = (warp & 1) * 32;
    int fr = lane >> 2;
    int fc = lane & 3;

    float acc[2][4][4];
#pragma unroll
    for (int i = 0; i < 2; i++)
#pragma unroll
        for (int j = 0; j < 4; j++)
#pragma unroll
            for (int q = 0; q < 4; q++) acc[i][j][q] = 0.0f;

    int arow[2], akc[2];
#pragma unroll
    for (int i = 0; i < 2; i++) {
        int idx = t + i * 256;
        arow[i] = idx >> 2;
        akc[i] = (idx & 3) * 4;
    }
    int bkr = t >> 4;
    int bnc = (t & 15) * 4;

    int grow[2];
#pragma unroll
    for (int i = 0; i < 2; i++) {
        int r = m0 + arow[i];
        grow[i] = (r < M) ? r : (M - 1);
    }

    uint32_t sA[2], sB;
#pragma unroll
    for (int i = 0; i < 2; i++)
        sA[i] = (uint32_t)__cvta_generic_to_shared(&As[0][arow[i]][akc[i]]);
    sB = (uint32_t)__cvta_generic_to_shared(&Bs[0][bkr][bnc]);
    const uint32_t stA = sizeof(As[0]);
    const uint32_t stB = sizeof(Bs[0]);

    auto prefetch = [&](int tile) {
        int k0 = tile << 4;
        int stg = tile % NSTAGE;
#pragma unroll
        for (int i = 0; i < 2; i++)
            cp16(sA[i] + stg * stA, &A[(size_t)grow[i] * K + k0 + akc[i]]);
        cp16(sB + stg * stB, &W[(size_t)(k0 + bkr) * HID + bnc]);
    };

    int T = K >> 4;

    prefetch(0);
    asm volatile("cp.async.commit_group;");
    prefetch(1);
    asm volatile("cp.async.commit_group;");

    for (int tt = 0; tt < T; ++tt) {
        asm volatile("cp.async.wait_group 1;");
        __syncthreads();
        if (tt + 2 < T) prefetch(tt + 2);
        asm volatile("cp.async.commit_group;");

        int buf = tt % NSTAGE;
#pragma unroll
        for (int kk = 0; kk < 16; kk += 8) {
            uint32_t af[2][4];
#pragma unroll
            for (int i = 0; i < 2; i++) {
                int rb = wm + i * 16 + fr;
                af[i][0] = f2tf32(As[buf][rb][kk + fc]);
                af[i][1] = f2tf32(As[buf][rb + 8][kk + fc]);
                af[i][2] = f2tf32(As[buf][rb][kk + fc + 4]);
                af[i][3] = f2tf32(As[buf][rb + 8][kk + fc + 4]);
            }
            uint32_t bf[4][2];
#pragma unroll
            for (int j = 0; j < 4; j++) {
                int nb = wn + j * 8 + fr;
                bf[j][0] = f2tf32(Bs[buf][kk + fc][nb]);
                bf[j][1] = f2tf32(Bs[buf][kk + fc + 4][nb]);
            }
#pragma unroll
            for (int i = 0; i < 2; i++)
#pragma unroll
                for (int j = 0; j < 4; j++)
                    mma_tf32(acc[i][j][0], acc[i][j][1], acc[i][j][2], acc[i][j][3],
                             af[i][0], af[i][1], af[i][2], af[i][3],
                             bf[j][0], bf[j][1]);
        }
    }

#pragma unroll
    for (int i = 0; i < 2; i++) {
#pragma unroll
        for (int j = 0; j < 4; j++) {
            int row = m0 + wm + i * 16 + fr;
            int col = wn + j * 8 + fc * 2;
            if (row < M)
                *reinterpret_cast<__half2*>(&g_XWH[(size_t)row * HID + col]) =
                    __floats2half2_rn(acc[i][j][0], acc[i][j][1]);
            if (row + 8 < M)
                *reinterpret_cast<__half2*>(&g_XWH[(size_t)(row + 8) * HID + col]) =
                    __floats2half2_rn(acc[i][j][2], acc[i][j][3]);
        }
    }
}

// ---------------------------------------------------------------------------
// Gather: warp per node, fp16 rows, packed int4 edge loads (2 edges / 16B).
// Lane owns channels {2l, 2l+1}. AGG[v] = sn*XW[v] + sum w_e * XW[src_e].
// ---------------------------------------------------------------------------

__global__ void gather_kernel(int N) {
    int gid = blockIdx.x * blockDim.x + threadIdx.x;
    int v = gid >> 5;
    int lane = gid & 31;
    if (v >= N) return;

    const __half2* XH2 = reinterpret_cast<const __half2*>(g_XWH);

    int beg = g_ROWPTR[v];
    int end = g_ROWPTR[v + 1];
    float dn = g_DINV[v];
    float sn = dn * dn;

    float2 self = __half22float2(XH2[v * 32 + lane]);
    float a0 = self.x * sn;
    float a1 = self.y * sn;

    int j = beg;
    if ((j & 1) && j < end) {
        int2 p = g_EPK[j];
        float2 x = __half22float2(XH2[p.x * 32 + lane]);
        float w = __int_as_float(p.y);
        a0 = fmaf(w, x.x, a0);
        a1 = fmaf(w, x.y, a1);
        j++;
    }
    for (; j + 3 < end; j += 4) {
        int4 pA = *reinterpret_cast<const int4*>(&g_EPK[j]);
        int4 pB = *reinterpret_cast<const int4*>(&g_EPK[j + 2]);
        float w0 = __int_as_float(pA.y);
        float w1 = __int_as_float(pA.w);
        float w2 = __int_as_float(pB.y);
        float w3 = __int_as_float(pB.w);
        float2 x0 = __half22float2(XH2[pA.x * 32 + lane]);
        float2 x1 = __half22float2(XH2[pA.z * 32 + lane]);
        float2 x2 = __half22float2(XH2[pB.x * 32 + lane]);
        float2 x3 = __half22float2(XH2[pB.z * 32 + lane]);
        a0 = fmaf(w0, x0.x, a0);
        a1 = fmaf(w0, x0.y, a1);
        a0 = fmaf(w1, x1.x, a0);
        a1 = fmaf(w1, x1.y, a1);
        a0 = fmaf(w2, x2.x, a0);
        a1 = fmaf(w2, x2.y, a1);
        a0 = fmaf(w3, x3.x, a0);
        a1 = fmaf(w3, x3.y, a1);
    }
    for (; j < end; ++j) {
        int2 p = g_EPK[j];
        float2 x = __half22float2(XH2[p.x * 32 + lane]);
        float w = __int_as_float(p.y);
        a0 = fmaf(w, x.x, a0);
        a1 = fmaf(w, x.y, a1);
    }

    *reinterpret_cast<float2*>(&g_AGG[v * HID + 2 * lane]) = make_float2(a0, a1);
}

// ---------------------------------------------------------------------------
// Fused BN stats + finalize + norm. 256 blocks (all resident -> spin safe).
// Phase 1: per-block partial sums (deterministic). Last block (ticket)
// reduces, writes g_SS, bumps g_EPOCH. Others spin on epoch. Phase 2: all
// blocks apply scale/shift/relu/residual and accumulate emb.
// ---------------------------------------------------------------------------

__global__ void __launch_bounds__(256)
bn_statsnorm_kernel(const float* __restrict__ gamma,
                    const float* __restrict__ beta,
                    const float* __restrict__ lw,
                    float4* __restrict__ EMB4,
                    int layer, int L, int N, int store_out) {
    __shared__ float4 ssum[256];
    __shared__ float4 ssq[256];
    __shared__ unsigned int sIsLast;
    const float4* AGG4 = reinterpret_cast<const float4*>(g_AGG);
    int t = threadIdx.x;
    int stride = gridDim.x * blockDim.x;    // 65536, multiple of 16
    int total = N * 16;

    // --- Phase 1: stats ---
    float4 s = make_float4(0.f, 0.f, 0.f, 0.f);
    float4 q = make_float4(0.f, 0.f, 0.f, 0.f);
    for (int i = blockIdx.x * blockDim.x + t; i < total; i += stride) {
        float4 v = AGG4[i];
        s.x += v.x; s.y += v.y; s.z += v.z; s.w += v.w;
        q.x += v.x * v.x; q.y += v.y * v.y; q.z += v.z * v.z; q.w += v.w * v.w;
    }
    ssum[t] = s;
    ssq[t] = q;
    __syncthreads();
    for (int off = 128; off >= 16; off >>= 1) {
        if (t < off) {
            float4 a = ssum[t], b = ssum[t + off];
            ssum[t] = make_float4(a.x + b.x, a.y + b.y, a.z + b.z, a.w + b.w);
            float4 c = ssq[t], d = ssq[t + off];
            ssq[t] = make_float4(c.x + d.x, c.y + d.y, c.z + d.z, c.w + d.w);
        }
        __syncthreads();
    }
    if (t < 16) {
        *reinterpret_cast<float4*>(&g_PART[blockIdx.x * 128 + t * 4]) = ssum[t];
        *reinterpret_cast<float4*>(&g_PART[blockIdx.x * 128 + 64 + t * 4]) = ssq[t];
    }
    __threadfence();
    __syncthreads();
    if (t == 0)
        sIsLast = (atomicAdd(&g_TICKET, 1u) == (unsigned)gridDim.x - 1u) ? 1u : 0u;
    __syncthreads();

    if (sIsLast) {
        if (t == 0) g_TICKET = 0;
        int c = t & 63;
        int g0 = t >> 6;
        float fs = 0.f, fq = 0.f;
        for (int g = g0; g < STATS_BLOCKS; g += 4) {
            fs += g_PART[g * 128 + c];
            fq += g_PART[g * 128 + 64 + c];
        }
        __syncthreads();
        float* s_s = reinterpret_cast<float*>(ssum);
        float* s_q = reinterpret_cast<float*>(ssq);
        s_s[t] = fs;
        s_q[t] = fq;
        __syncthreads();
        if (t < 128) { s_s[t] += s_s[t + 128]; s_q[t] += s_q[t + 128]; }
        __syncthreads();
        if (t < 64) {
            float S = s_s[t] + s_s[t + 64];
            float Q = s_q[t] + s_q[t + 64];
            float invN = 1.0f / (float)N;
            float mean = S * invN;
            float var = Q * invN - mean * mean;
            float inv = rsqrtf(var + 1e-5f);
            float sc = gamma[layer * HID + c] * inv;
            g_SS[c] = sc;
            g_SS[64 + c] = beta[layer * HID + c] - mean * sc;
        }
        if (t == 0) {
            float se = 0.f;
            for (int j = 0; j < L; j++) se += expf(lw[j]);
            g_SS[128] = expf(lw[layer]) / se;
        }
        __threadfence();
        __syncthreads();
        if (t == 0) atomicExch(&g_EPOCH, layer + 1);   // release
    } else {
        if (t == 0) {
            while (atomicAdd(&g_EPOCH, 0) < layer + 1) { }
        }
        __syncthreads();
    }

    // --- Phase 2: norm (g_SS fresh via __ldcg; L1 clean at launch anyway) ---
    const float4* PREV4 = reinterpret_cast<const float4*>((layer & 1) ? g_OUT0 : g_OUT1);
    float4* OUT4        = reinterpret_cast<float4*>((layer & 1) ? g_OUT1 : g_OUT0);

    int t0 = blockIdx.x * blockDim.x + t;
    int c4 = (t0 & 15) * 4;
    float4 sc = __ldcg(reinterpret_cast<const float4*>(&g_SS[c4]));
    float4 sh = __ldcg(reinterpret_cast<const float4*>(&g_SS[64 + c4]));
    float w = __ldcg(&g_SS[128]);
    for (int i = t0; i < total; i += stride) {
        float4 v = AGG4[i];
        float4 o;
        o.x = fmaxf(fmaf(v.x, sc.x, sh.x), 0.f);
        o.y = fmaxf(fmaf(v.y, sc.y, sh.y), 0.f);
        o.z = fmaxf(fmaf(v.z, sc.z, sh.z), 0.f);
        o.w = fmaxf(fmaf(v.w, sc.w, sh.w), 0.f);
        if (layer > 0) {
            float4 p = PREV4[i];
            o.x = fmaf(0.7f, p.x, o.x);
            o.y = fmaf(0.7f, p.y, o.y);
            o.z = fmaf(0.7f, p.z, o.z);
            o.w = fmaf(0.7f, p.w, o.w);
        }
        if (store_out) OUT4[i] = o;
        if (layer == 0) {
            EMB4[i] = make_float4(w * o.x, w * o.y, w * o.z, w * o.w);
        } else {
            float4 e = EMB4[i];
            e.x = fmaf(w, o.x, e.x);
            e.y = fmaf(w, o.y, e.y);
            e.z = fmaf(w, o.z, e.z);
            e.w = fmaf(w, o.w, e.w);
            EMB4[i] = e;
        }
    }
}

// ---------------------------------------------------------------------------
// Host launcher — kernel launches only; layer-0 GEMM at launch #4 (profiled).
// ---------------------------------------------------------------------------

extern "C" void kernel_launch(void* const* d_in, const int* in_sizes, int n_in,
                              void* d_out, int out_size) {
    const float* feat  = (const float*)d_in[0];
    const int* ewords  = (const int*)d_in[1];
    const float* W0    = (const float*)d_in[2];
    const float* Wh    = (const float*)d_in[4];
    const float* gamma = (const float*)d_in[6];
    const float* beta  = (const float*)d_in[7];
    const float* lw    = (const float*)d_in[8];
    float* out         = (float*)d_out;

    int hid    = in_sizes[3];
    int in_dim = in_sizes[2] / hid;
    int N      = in_sizes[0] / in_dim;
    int E      = in_sizes[1] / 2;
    int L      = in_sizes[8];

    int nb = (N + SBS - 1) / SBS;
    int gemm_blocks = (N + 127) / 128;
    int gather_blocks = (N * 32 + 255) / 256;   // warp per node

    init_detect_kernel<<<(N + 255) / 256, 256>>>(ewords, N, E);              // 1
    count_kernel<<<(E + 255) / 256, 256>>>(ewords, E);                       // 2
    dinv_kernel<<<(N + 255) / 256, 256>>>(N);                                // 3
    gemm_tf32_kernel<<<gemm_blocks, 256>>>(feat, 0, W0, N, in_dim);          // 4 (profiled)
    scan1_kernel<<<nb, SBS>>>(N);                                            // 5
    scan2_kernel<<<1, SBS>>>(nb);                                            // 6
    scan3_kernel<<<(N + 255) / 256, 256>>>(N, E);                            // 7
    fill_kernel<<<(E + 255) / 256, 256>>>(ewords, E);                        // 8

    for (int layer = 0; layer < L; layer++) {
        if (layer > 0) {
            int src_sel = ((layer - 1) & 1) ? 2 : 1;
            const float* W = Wh + (size_t)(layer - 1) * hid * hid;
            gemm_tf32_kernel<<<gemm_blocks, 256>>>(feat, src_sel, W, N, hid);
        }
        gather_kernel<<<gather_blocks, 256>>>(N);
        bn_statsnorm_kernel<<<STATS_BLOCKS, 256>>>(gamma, beta, lw, (float4*)out,
                                                   layer, L, N, layer < L - 1 ? 1 : 0);
    }
}

// round 13
// speedup vs baseline: 1.0515x; 1.0515x over previous
#include <cuda_runtime.h>
#include <cuda_fp16.h>
#include <cstdint>

// ---------------------------------------------------------------------------
// PopulationGNN: 4-layer GCN, N=50000, IN_DIM=2000, HID=64, E=1.6M
// CSR build once (packed src+weight), then per layer:
// TF32 mma GEMM (cp.async.cg 3-stage, raw-fp32-bits "fast tf32", fp16 out)
// -> warp-per-node gather (packed int4 edge loads)
// -> BN stats+finalize (256-block ticket) -> norm/relu/res/emb fused.
// ---------------------------------------------------------------------------

#define HID 64
#define MAXN 50048
#define MAXE 1600256
#define STATS_BLOCKS 256
#define SBS 256
#define MAXSB 256

__device__ __align__(16) __half g_XWH[MAXN * HID];   // fp16 XW (gather input)
__device__ __align__(16) float g_AGG[MAXN * HID];
__device__ __align__(16) float g_OUT0[MAXN * HID];
__device__ __align__(16) float g_OUT1[MAXN * HID];
__device__ int   g_DEGI[MAXN];
__device__ float g_DINV[MAXN];
__device__ __align__(16) int2 g_EPK[MAXE];           // packed {src, weight-bits}
__device__ int   g_ROWPTR[MAXN + 1];
__device__ int   g_CUR[MAXN];
__device__ int   g_ROWEXC[MAXN];
__device__ int   g_BTOT[MAXSB];
__device__ int   g_BOFF[MAXSB];
__device__ int   g_IS32;
__device__ unsigned int g_TICKET;
__device__ __align__(16) float g_PART[STATS_BLOCKS * 128];
__device__ __align__(16) float g_SS[132];

// ---------------------------------------------------------------------------
// Setup: fused init+detect, then CSR build
// ---------------------------------------------------------------------------

__global__ void init_detect_kernel(const int* __restrict__ words, int n, int E) {
    int i = blockIdx.x * blockDim.x + threadIdx.x;
    if (i < n) g_DEGI[i] = 0;
    if (i == 0) { g_IS32 = 0; g_TICKET = 0; }
    int idx = 2 * i + 1;
    if (idx < E && words[idx] != 0)
        atomicOr(&g_IS32, 1);
}

__device__ __forceinline__ void decode_edge(const int* __restrict__ words, int E, int e,
                                            int& s, int& d) {
    if (g_IS32) {
        s = words[e];
        d = words[E + e];
    } else {
        s = words[2 * e];
        d = words[2 * E + 2 * e];
    }
}

__global__ void count_kernel(const int* __restrict__ words, int E) {
    int e = blockIdx.x * blockDim.x + threadIdx.x;
    if (e < E) {
        int s, d;
        decode_edge(words, E, e, s, d);
        atomicAdd(&g_DEGI[d], 1);
    }
}

__global__ void dinv_kernel(int n) {
    int i = blockIdx.x * blockDim.x + threadIdx.x;
    if (i < n) g_DINV[i] = rsqrtf((float)g_DEGI[i] + 1.0f);
}

__global__ void scan1_kernel(int n) {
    __shared__ int sm[SBS];
    int t = threadIdx.x;
    int i = blockIdx.x * SBS + t;
    int v = (i < n) ? g_DEGI[i] : 0;
    sm[t] = v;
    __syncthreads();
#pragma unroll
    for (int off = 1; off < SBS; off <<= 1) {
        int y = (t >= off) ? sm[t - off] : 0;
        __syncthreads();
        sm[t] += y;
        __syncthreads();
    }
    if (i < n) g_ROWEXC[i] = sm[t] - v;
    if (t == SBS - 1) g_BTOT[blockIdx.x] = sm[t];
}

__global__ void scan2_kernel(int nb) {
    __shared__ int sm[SBS];
    int t = threadIdx.x;
    int v = (t < nb) ? g_BTOT[t] : 0;
    sm[t] = v;
    __syncthreads();
#pragma unroll
    for (int off = 1; off < SBS; off <<= 1) {
        int y = (t >= off) ? sm[t - off] : 0;
        __syncthreads();
        sm[t] += y;
        __syncthreads();
    }
    if (t < nb) g_BOFF[t] = sm[t] - v;
}

__global__ void scan3_kernel(int n, int E) {
    int i = blockIdx.x * blockDim.x + threadIdx.x;
    if (i < n) {
        int r = g_ROWEXC[i] + g_BOFF[i / SBS];
        g_ROWPTR[i] = r;
        g_CUR[i] = r;
    }
    if (i == 0) g_ROWPTR[n] = E;
}

__global__ void fill_kernel(const int* __restrict__ words, int E) {
    int e = blockIdx.x * blockDim.x + threadIdx.x;
    if (e < E) {
        int s, d;
        decode_edge(words, E, e, s, d);
        int pos = atomicAdd(&g_CUR[d], 1);
        float w = g_DINV[s] * g_DINV[d];
        g_EPK[pos] = make_int2(s, __float_as_int(w));
    }
}

// ---------------------------------------------------------------------------
// TF32 GEMM, cp.async.cg 3-stage pipeline, raw-bits fast-tf32 fragments.
// A[M,K] @ W[K,64] -> g_XWH (fp16). BM=128, BN=64, BK=16, 256 thr, 8 warps,
// warp tile 32x32 via m16n8k8. HW truncates fp32 operand bits to tf32.
// ---------------------------------------------------------------------------

#define NSTAGE 3

__device__ __forceinline__ void mma_tf32(float& c0, float& c1, float& c2, float& c3,
                                         uint32_t a0, uint32_t a1, uint32_t a2, uint32_t a3,
                                         uint32_t b0, uint32_t b1) {
    asm volatile(
        "mma.sync.aligned.m16n8k8.row.col.f32.tf32.tf32.f32 "
        "{%0,%1,%2,%3}, {%4,%5,%6,%7}, {%8,%9}, {%0,%1,%2,%3};"
        : "+f"(c0), "+f"(c1), "+f"(c2), "+f"(c3)
        : "r"(a0), "r"(a1), "r"(a2), "r"(a3), "r"(b0), "r"(b1));
}

__device__ __forceinline__ void cp16(uint32_t smem_addr, const float* gptr) {
    asm volatile("cp.async.cg.shared.global [%0], [%1], 16;"
                 :: "r"(smem_addr), "l"(gptr));
}

__global__ void __launch_bounds__(256, 3)
gemm_tf32_kernel(const float* __restrict__ feat, int src_sel,
                 const float* __restrict__ W, int M, int K) {
    __shared__ uint32_t As[NSTAGE][128][20];   // raw fp32 bits; banks (20m+k)%32 ok
    __shared__ uint32_t Bs[NSTAGE][16][72];    // raw fp32 bits; banks (8k+n)%32 ok

    const float* A = (src_sel == 0) ? feat : (src_sel == 1 ? g_OUT0 : g_OUT1);

    int t = threadIdx.x;
    int m0 = blockIdx.x * 128;
    int warp = t >> 5;
    int lane = t & 31;
    int wm = (warp >> 1) * 32;
    int wn = (warp & 1) * 32;
    int fr = lane >> 2;
    int fc = lane & 3;

    float acc[2][4][4];
#pragma unroll
    for (int i = 0; i < 2; i++)
#pragma unroll
        for (int j = 0; j < 4; j++)
#pragma unroll
            for (int q = 0; q < 4; q++) acc[i][j][q] = 0.0f;

    int arow[2], akc[2];
#pragma unroll
    for (int i = 0; i < 2; i++) {
        int idx = t + i * 256;
        arow[i] = idx >> 2;
        akc[i] = (idx & 3) * 4;
    }
    int bkr = t >> 4;
    int bnc = (t & 15) * 4;

    int grow[2];
#pragma unroll
    for (int i = 0; i < 2; i++) {
        int r = m0 + arow[i];
        grow[i] = (r < M) ? r : (M - 1);
    }

    uint32_t sA[2], sB;
#pragma unroll
    for (int i = 0; i < 2; i++)
        sA[i] = (uint32_t)__cvta_generic_to_shared(&As[0][arow[i]][akc[i]]);
    sB = (uint32_t)__cvta_generic_to_shared(&Bs[0][bkr][bnc]);
    const uint32_t stA = sizeof(As[0]);
    const uint32_t stB = sizeof(Bs[0]);

    auto prefetch = [&](int tile) {
        int k0 = tile << 4;
        int stg = tile % NSTAGE;
#pragma unroll
        for (int i = 0; i < 2; i++)
            cp16(sA[i] + stg * stA, &A[(size_t)grow[i] * K + k0 + akc[i]]);
        cp16(sB + stg * stB, &W[(size_t)(k0 + bkr) * HID + bnc]);
    };

    int T = K >> 4;

    prefetch(0);
    asm volatile("cp.async.commit_group;");
    prefetch(1);
    asm volatile("cp.async.commit_group;");

    for (int tt = 0; tt < T; ++tt) {
        asm volatile("cp.async.wait_group 1;");
        __syncthreads();
        if (tt + 2 < T) prefetch(tt + 2);
        asm volatile("cp.async.commit_group;");

        int buf = tt % NSTAGE;
#pragma unroll
        for (int kk = 0; kk < 16; kk += 8) {
            uint32_t af[2][4];
#pragma unroll
            for (int i = 0; i < 2; i++) {
                int rb = wm + i * 16 + fr;
                af[i][0] = As[buf][rb][kk + fc];
                af[i][1] = As[buf][rb + 8][kk + fc];
                af[i][2] = As[buf][rb][kk + fc + 4];
                af[i][3] = As[buf][rb + 8][kk + fc + 4];
            }
            uint32_t bf[4][2];
#pragma unroll
            for (int j = 0; j < 4; j++) {
                int nb = wn + j * 8 + fr;
                bf[j][0] = Bs[buf][kk + fc][nb];
                bf[j][1] = Bs[buf][kk + fc + 4][nb];
            }
#pragma unroll
            for (int i = 0; i < 2; i++)
#pragma unroll
                for (int j = 0; j < 4; j++)
                    mma_tf32(acc[i][j][0], acc[i][j][1], acc[i][j][2], acc[i][j][3],
                             af[i][0], af[i][1], af[i][2], af[i][3],
                             bf[j][0], bf[j][1]);
        }
    }

#pragma unroll
    for (int i = 0; i < 2; i++) {
#pragma unroll
        for (int j = 0; j < 4; j++) {
            int row = m0 + wm + i * 16 + fr;
            int col = wn + j * 8 + fc * 2;
            if (row < M)
                *reinterpret_cast<__half2*>(&g_XWH[(size_t)row * HID + col]) =
                    __floats2half2_rn(acc[i][j][0], acc[i][j][1]);
            if (row + 8 < M)
                *reinterpret_cast<__half2*>(&g_XWH[(size_t)(row + 8) * HID + col]) =
                    __floats2half2_rn(acc[i][j][2], acc[i][j][3]);
        }
    }
}

// ---------------------------------------------------------------------------
// Gather: warp per node, fp16 rows, packed int4 edge loads (2 edges / 16B).
// Lane owns channels {2l, 2l+1}. AGG[v] = sn*XW[v] + sum w_e * XW[src_e].
// ---------------------------------------------------------------------------

__global__ void gather_kernel(int N) {
    int gid = blockIdx.x * blockDim.x + threadIdx.x;
    int v = gid >> 5;
    int lane = gid & 31;
    if (v >= N) return;

    const __half2* XH2 = reinterpret_cast<const __half2*>(g_XWH);

    int beg = g_ROWPTR[v];
    int end = g_ROWPTR[v + 1];
    float dn = g_DINV[v];
    float sn = dn * dn;

    float2 self = __half22float2(XH2[v * 32 + lane]);
    float a0 = self.x * sn;
    float a1 = self.y * sn;

    int j = beg;
    if ((j & 1) && j < end) {
        int2 p = g_EPK[j];
        float2 x = __half22float2(XH2[p.x * 32 + lane]);
        float w = __int_as_float(p.y);
        a0 = fmaf(w, x.x, a0);
        a1 = fmaf(w, x.y, a1);
        j++;
    }
    for (; j + 3 < end; j += 4) {
        int4 pA = *reinterpret_cast<const int4*>(&g_EPK[j]);
        int4 pB = *reinterpret_cast<const int4*>(&g_EPK[j + 2]);
        float w0 = __int_as_float(pA.y);
        float w1 = __int_as_float(pA.w);
        float w2 = __int_as_float(pB.y);
        float w3 = __int_as_float(pB.w);
        float2 x0 = __half22float2(XH2[pA.x * 32 + lane]);
        float2 x1 = __half22float2(XH2[pA.z * 32 + lane]);
        float2 x2 = __half22float2(XH2[pB.x * 32 + lane]);
        float2 x3 = __half22float2(XH2[pB.z * 32 + lane]);
        a0 = fmaf(w0, x0.x, a0);
        a1 = fmaf(w0, x0.y, a1);
        a0 = fmaf(w1, x1.x, a0);
        a1 = fmaf(w1, x1.y, a1);
        a0 = fmaf(w2, x2.x, a0);
        a1 = fmaf(w2, x2.y, a1);
        a0 = fmaf(w3, x3.x, a0);
        a1 = fmaf(w3, x3.y, a1);
    }
    for (; j < end; ++j) {
        int2 p = g_EPK[j];
        float2 x = __half22float2(XH2[p.x * 32 + lane]);
        float w = __int_as_float(p.y);
        a0 = fmaf(w, x.x, a0);
        a1 = fmaf(w, x.y, a1);
    }

    *reinterpret_cast<float2*>(&g_AGG[v * HID + 2 * lane]) = make_float2(a0, a1);
}

// ---------------------------------------------------------------------------
// BN stats + finalize fused (256 blocks, deterministic last-block ticket)
// ---------------------------------------------------------------------------

__global__ void bn_stats_fin_kernel(const float* __restrict__ gamma,
                                    const float* __restrict__ beta,
                                    const float* __restrict__ lw,
                                    int layer, int L, int N) {
    __shared__ float4 ssum[256];
    __shared__ float4 ssq[256];
    __shared__ unsigned int sIsLast;
    const float4* AGG4 = reinterpret_cast<const float4*>(g_AGG);
    int t = threadIdx.x;
    int stride = gridDim.x * blockDim.x;
    int total = N * 16;
    float4 s = make_float4(0.f, 0.f, 0.f, 0.f);
    float4 q = make_float4(0.f, 0.f, 0.f, 0.f);
    for (int i = blockIdx.x * blockDim.x + t; i < total; i += stride) {
        float4 v = AGG4[i];
        s.x += v.x; s.y += v.y; s.z += v.z; s.w += v.w;
        q.x += v.x * v.x; q.y += v.y * v.y; q.z += v.z * v.z; q.w += v.w * v.w;
    }
    ssum[t] = s;
    ssq[t] = q;
    __syncthreads();
    for (int off = 128; off >= 16; off >>= 1) {
        if (t < off) {
            float4 a = ssum[t], b = ssum[t + off];
            ssum[t] = make_float4(a.x + b.x, a.y + b.y, a.z + b.z, a.w + b.w);
            float4 c = ssq[t], d = ssq[t + off];
            ssq[t] = make_float4(c.x + d.x, c.y + d.y, c.z + d.z, c.w + d.w);
        }
        __syncthreads();
    }
    if (t < 16) {
        *reinterpret_cast<float4*>(&g_PART[blockIdx.x * 128 + t * 4]) = ssum[t];
        *reinterpret_cast<float4*>(&g_PART[blockIdx.x * 128 + 64 + t * 4]) = ssq[t];
    }
    __threadfence();
    __syncthreads();
    if (t == 0)
        sIsLast = (atomicAdd(&g_TICKET, 1u) == (unsigned)gridDim.x - 1u) ? 1u : 0u;
    __syncthreads();
    if (!sIsLast) return;

    if (t == 0) g_TICKET = 0;
    int c = t & 63;
    int g0 = t >> 6;
    float fs = 0.f, fq = 0.f;
    for (int g = g0; g < STATS_BLOCKS; g += 4) {
        fs += g_PART[g * 128 + c];
        fq += g_PART[g * 128 + 64 + c];
    }
    __syncthreads();
    float* s_s = reinterpret_cast<float*>(ssum);
    float* s_q = reinterpret_cast<float*>(ssq);
    s_s[t] = fs;
    s_q[t] = fq;
    __syncthreads();
    if (t < 128) { s_s[t] += s_s[t + 128]; s_q[t] += s_q[t + 128]; }
    __syncthreads();
    if (t < 64) {
        float S = s_s[t] + s_s[t + 64];
        float Q = s_q[t] + s_q[t + 64];
        float invN = 1.0f / (float)N;
        float mean = S * invN;
        float var = Q * invN - mean * mean;
        float inv = rsqrtf(var + 1e-5f);
        float sc = gamma[layer * HID + c] * inv;
        g_SS[c] = sc;
        g_SS[64 + c] = beta[layer * HID + c] - mean * sc;
    }
    if (t == 0) {
        float se = 0.f;
        for (int j = 0; j < L; j++) se += expf(lw[j]);
        g_SS[128] = expf(lw[layer]) / se;
    }
}

// ---------------------------------------------------------------------------
// Normalize + ReLU + residual + softmax-weighted emb accumulation.
// Last layer's OUT is never read again -> store skipped (store_out=0).
// ---------------------------------------------------------------------------

__global__ void bn_norm_kernel(float4* __restrict__ EMB4, int N, int layer, int store_out) {
    const float4* AGG4  = reinterpret_cast<const float4*>(g_AGG);
    const float4* PREV4 = reinterpret_cast<const float4*>((layer & 1) ? g_OUT0 : g_OUT1);
    float4* OUT4        = reinterpret_cast<float4*>((layer & 1) ? g_OUT1 : g_OUT0);

    int t0 = blockIdx.x * blockDim.x + threadIdx.x;
    int c4 = (t0 & 15) * 4;
    float4 sc = *reinterpret_cast<const float4*>(&g_SS[c4]);
    float4 sh = *reinterpret_cast<const float4*>(&g_SS[64 + c4]);
    float w = g_SS[128];
    int total = N * 16;
    int stride = gridDim.x * blockDim.x;
    for (int i = t0; i < total; i += stride) {
        float4 v = AGG4[i];
        float4 o;
        o.x = fmaxf(fmaf(v.x, sc.x, sh.x), 0.f);
        o.y = fmaxf(fmaf(v.y, sc.y, sh.y), 0.f);
        o.z = fmaxf(fmaf(v.z, sc.z, sh.z), 0.f);
        o.w = fmaxf(fmaf(v.w, sc.w, sh.w), 0.f);
        if (layer > 0) {
            float4 p = PREV4[i];
            o.x = fmaf(0.7f, p.x, o.x);
            o.y = fmaf(0.7f, p.y, o.y);
            o.z = fmaf(0.7f, p.z, o.z);
            o.w = fmaf(0.7f, p.w, o.w);
        }
        if (store_out) OUT4[i] = o;
        if (layer == 0) {
            EMB4[i] = make_float4(w * o.x, w * o.y, w * o.z, w * o.w);
        } else {
            float4 e = EMB4[i];
            e.x = fmaf(w, o.x, e.x);
            e.y = fmaf(w, o.y, e.y);
            e.z = fmaf(w, o.z, e.z);
            e.w = fmaf(w, o.w, e.w);
            EMB4[i] = e;
        }
    }
}

// ---------------------------------------------------------------------------
// Host launcher — kernel launches only; layer-0 GEMM at launch #4 (profiled).
// ---------------------------------------------------------------------------

extern "C" void kernel_launch(void* const* d_in, const int* in_sizes, int n_in,
                              void* d_out, int out_size) {
    const float* feat  = (const float*)d_in[0];
    const int* ewords  = (const int*)d_in[1];
    const float* W0    = (const float*)d_in[2];
    const float* Wh    = (const float*)d_in[4];
    const float* gamma = (const float*)d_in[6];
    const float* beta  = (const float*)d_in[7];
    const float* lw    = (const float*)d_in[8];
    float* out         = (float*)d_out;

    int hid    = in_sizes[3];
    int in_dim = in_sizes[2] / hid;
    int N      = in_sizes[0] / in_dim;
    int E      = in_sizes[1] / 2;
    int L      = in_sizes[8];

    int nb = (N + SBS - 1) / SBS;
    int gemm_blocks = (N + 127) / 128;
    int gather_blocks = (N * 32 + 255) / 256;   // warp per node

    init_detect_kernel<<<(N + 255) / 256, 256>>>(ewords, N, E);              // 1
    count_kernel<<<(E + 255) / 256, 256>>>(ewords, E);                       // 2
    dinv_kernel<<<(N + 255) / 256, 256>>>(N);                                // 3
    gemm_tf32_kernel<<<gemm_blocks, 256>>>(feat, 0, W0, N, in_dim);          // 4 (profiled)
    scan1_kernel<<<nb, SBS>>>(N);                                            // 5
    scan2_kernel<<<1, SBS>>>(nb);                                            // 6
    scan3_kernel<<<(N + 255) / 256, 256>>>(N, E);                            // 7
    fill_kernel<<<(E + 255) / 256, 256>>>(ewords, E);                        // 8

    for (int layer = 0; layer < L; layer++) {
        if (layer > 0) {
            int src_sel = ((layer - 1) & 1) ? 2 : 1;
            const float* W = Wh + (size_t)(layer - 1) * hid * hid;
            gemm_tf32_kernel<<<gemm_blocks, 256>>>(feat, src_sel, W, N, hid);
        }
        gather_kernel<<<gather_blocks, 256>>>(N);
        bn_stats_fin_kernel<<<STATS_BLOCKS, 256>>>(gamma, beta, lw, layer, L, N);
        bn_norm_kernel<<<512, 256>>>((float4*)out, N, layer, layer < L - 1 ? 1 : 0);
    }
}